// round 15
// baseline (speedup 1.0000x reference)
#include <cuda_runtime.h>
#include <cuda_fp16.h>
#include <math.h>
#include <stdint.h>

#define DM 768
#define DFF 3072
#define NH 12
#define DK 64
#define BATCH 2
#define SEQ 2048
#define MROWS (BATCH*SEQ)            // 4096
#define BHN (BATCH*NH)               // 24
#define QKVS 2304                    // packed QKV row stride
#define OUT_ELEMS (MROWS*DM)
#define ATT_ELEMS ((size_t)BHN*SEQ*SEQ)

// ---- scratch (allocation-free: __device__ globals) ----
__device__ __align__(16) __half g_xh  [MROWS*DM];
__device__ __align__(16) __half g_Wqkv[DM*QKVS];
__device__ __align__(16) float  g_bqkv[QKVS];
__device__ __align__(16) __half g_Woh[DM*DM];
__device__ __align__(16) __half g_W1h[DM*DFF];
__device__ __align__(16) __half g_W2h[DFF*DM];
__device__ __align__(16) __half g_qkvh[MROWS*QKVS];
__device__ __align__(16) __half g_Ph [BHN*(size_t)SEQ*SEQ];  // fp16 normalized P
__device__ __align__(16) __half g_ctxh[MROWS*DM];
__device__ __align__(16) __half g_aoh[MROWS*DM];
__device__ __align__(16) __half g_hh [MROWS*DFF];
__device__ __align__(16) float  g_part [BHN*16*SEQ*2];  // (m_t, s_t) per row,tile
__device__ __align__(16) float  g_stats[BHN*(size_t)SEQ*2]; // (m, 1/s) per row
__device__ __align__(16) float  g_P[BHN*(size_t)SEQ*SEQ];   // fallback attn
__device__ __align__(16) float  g_t0[MROWS*DM];
__device__ __align__(16) float  g_ao[MROWS*DM];
__device__ __align__(16) float  g_f [MROWS*DM];

__device__ __forceinline__ uint32_t smem_u32(const void* p) {
    uint32_t a;
    asm("{ .reg .u64 t; cvta.to.shared.u64 t, %1; cvt.u32.u64 %0, t; }"
        : "=r"(a) : "l"(p));
    return a;
}

__device__ __forceinline__ void mma16816(float* c, const uint32_t* a, const uint32_t* b) {
    asm volatile(
        "mma.sync.aligned.m16n8k16.row.col.f32.f16.f16.f32 "
        "{%0,%1,%2,%3}, {%4,%5,%6,%7}, {%8,%9}, {%0,%1,%2,%3};"
        : "+f"(c[0]), "+f"(c[1]), "+f"(c[2]), "+f"(c[3])
        : "r"(a[0]), "r"(a[1]), "r"(a[2]), "r"(a[3]), "r"(b[0]), "r"(b[1]));
}

#define LDSM_X4(r0,r1,r2,r3,addr) \
    asm volatile("ldmatrix.sync.aligned.m8n8.x4.shared.b16 {%0,%1,%2,%3}, [%4];" \
        : "=r"(r0),"=r"(r1),"=r"(r2),"=r"(r3) : "r"(addr))
#define LDSM_X4T(r0,r1,r2,r3,addr) \
    asm volatile("ldmatrix.sync.aligned.m8n8.x4.trans.shared.b16 {%0,%1,%2,%3}, [%4];" \
        : "=r"(r0),"=r"(r1),"=r"(r2),"=r"(r3) : "r"(addr))
#define CP_ASYNC16(saddr, gptr) \
    asm volatile("cp.async.cg.shared.global [%0], [%1], 16;" :: "r"(saddr), "l"(gptr))
#define CP_COMMIT() asm volatile("cp.async.commit_group;")
#define CP_WAIT_GROUP(n) asm volatile("cp.async.wait_group %0;" :: "n"(n))

// ============================================================
// f32 -> f16 convert
// ============================================================
__global__ __launch_bounds__(256) void f2h_kernel(
    const float* __restrict__ X, __half* __restrict__ Y)
{
    int i = (blockIdx.x * 256 + threadIdx.x) * 4;
    float4 v = *(const float4*)(X + i);
    *(__half2*)(Y + i)     = __floats2half2_rn(v.x, v.y);
    *(__half2*)(Y + i + 2) = __floats2half2_rn(v.z, v.w);
}

// ============================================================
// pack Wq|Wk|Wv -> [768, 2304] fp16 ; biases -> [2304] f32
// ============================================================
__global__ __launch_bounds__(256) void pack_qkv_w(
    const float* __restrict__ Wq, const float* __restrict__ Wk,
    const float* __restrict__ Wv, __half* __restrict__ Wout)
{
    int i = (blockIdx.x * 256 + threadIdx.x) * 4;   // grid covers 768*2304
    int r = i / QKVS, c = i % QKVS;
    const float* src; int cc;
    if (c < 768)       { src = Wq; cc = c; }
    else if (c < 1536) { src = Wk; cc = c - 768; }
    else               { src = Wv; cc = c - 1536; }
    float4 v = *(const float4*)(src + (size_t)r * DM + cc);
    *(__half2*)(Wout + i)     = __floats2half2_rn(v.x, v.y);
    *(__half2*)(Wout + i + 2) = __floats2half2_rn(v.z, v.w);
}

__global__ __launch_bounds__(256) void pack_qkv_b(
    const float* __restrict__ bq, const float* __restrict__ bk,
    const float* __restrict__ bv, float* __restrict__ bout)
{
    int c = blockIdx.x * 256 + threadIdx.x;
    if (c >= QKVS) return;
    float v;
    if (c < 768)       v = bq[c];
    else if (c < 1536) v = bk[c - 768];
    else               v = bv[c - 1536];
    bout[c] = v;
}

// ============================================================
// fp16 GEMM: 128x128x32, 3-stage cp.async, ldmatrix frags, 8 warps.
// ============================================================
template<int RELU, int OUTF32, int OUTHALF>
__global__ __launch_bounds__(256, 2) void hgemm(
    const __half* __restrict__ A, const __half* __restrict__ W,
    const float* __restrict__ bias, const float* __restrict__ resid,
    float* __restrict__ C, __half* __restrict__ Ch,
    int M, int N, int K)
{
    extern __shared__ char dsm[];
    uint32_t sb = smem_u32(dsm);

    int tid = threadIdx.x, lane = tid & 31, warp = tid >> 5;
    int wm = warp >> 1, wn = warp & 1;
    int g = lane >> 2, tg = lane & 3;
    int bm = blockIdx.y * 128, bn = blockIdx.x * 128;

    float acc[2][8][4];
#pragma unroll
    for (int mt = 0; mt < 2; mt++)
#pragma unroll
        for (int nt = 0; nt < 8; nt++)
#pragma unroll
            for (int q = 0; q < 4; q++) acc[mt][nt][q] = 0.f;

    const int NC = K / 32;
    int ar0 = tid >> 2, ac0 = tid & 3;
    int bk0 = tid >> 4, bc0 = tid & 15;

#define LOAD_STAGE(stg, k0) { \
    uint32_t base = sb + (stg) * 16384; \
    _Pragma("unroll") \
    for (int j = 0; j < 2; j++) { \
        int r = ar0 + j * 64, c = ac0; \
        uint32_t sa = base + r * 64 + ((c ^ ((r >> 1) & 3)) << 4); \
        CP_ASYNC16(sa, A + (size_t)(bm + r) * K + (k0) + c * 8); \
    } \
    _Pragma("unroll") \
    for (int j = 0; j < 2; j++) { \
        int k = bk0 + j * 16, c = bc0; \
        uint32_t sa = base + 8192 + k * 256 + ((c ^ (k & 7)) << 4); \
        CP_ASYNC16(sa, W + (size_t)((k0) + k) * N + bn + c * 8); \
    } \
    CP_COMMIT(); }

    LOAD_STAGE(0, 0);
    LOAD_STAGE(1, 32);

    int st = 0;
    for (int i = 0; i < NC; i++) {
        CP_WAIT_GROUP(1);
        __syncthreads();
        if (i + 2 < NC) {
            int st2 = st + 2; if (st2 >= 3) st2 -= 3;
            LOAD_STAGE(st2, (i + 2) * 32);
        } else {
            CP_COMMIT();
        }
        uint32_t base = sb + st * 16384;
#pragma unroll
        for (int kk = 0; kk < 2; kk++) {
            int ks16 = kk * 16;
            uint32_t a[2][4];
#pragma unroll
            for (int mt = 0; mt < 2; mt++) {
                int row = wm * 32 + mt * 16 + (lane & 15);
                int ch = (ks16 >> 3) + (lane >> 4);
                uint32_t ad = base + row * 64 + ((ch ^ ((row >> 1) & 3)) << 4);
                LDSM_X4(a[mt][0], a[mt][1], a[mt][2], a[mt][3], ad);
            }
#pragma unroll
            for (int p = 0; p < 4; p++) {
                int k = ks16 + (lane & 15);
                int ch = wn * 8 + p * 2 + (lane >> 4);
                uint32_t bd = base + 8192 + k * 256 + ((ch ^ (k & 7)) << 4);
                uint32_t b0, b1, b2, b3;
                LDSM_X4T(b0, b1, b2, b3, bd);
                uint32_t f0[2] = {b0, b1}, f1[2] = {b2, b3};
#pragma unroll
                for (int mt = 0; mt < 2; mt++) {
                    mma16816(acc[mt][2*p],     a[mt], f0);
                    mma16816(acc[mt][2*p + 1], a[mt], f1);
                }
            }
        }
        st++; if (st >= 3) st = 0;
    }
#undef LOAD_STAGE

#pragma unroll
    for (int mt = 0; mt < 2; mt++) {
#pragma unroll
        for (int nt = 0; nt < 8; nt++) {
            int c = bn + wn * 64 + nt * 8 + tg * 2;
            float bx = bias[c], by = bias[c + 1];
#pragma unroll
            for (int hh = 0; hh < 2; hh++) {
                int r = bm + wm * 32 + mt * 16 + g + hh * 8;
                float v0 = acc[mt][nt][hh*2+0] + bx;
                float v1 = acc[mt][nt][hh*2+1] + by;
                if (OUTF32 && resid) {
                    float2 rv = *(const float2*)(resid + (size_t)r * N + c);
                    v0 += rv.x; v1 += rv.y;
                }
                if (RELU) { v0 = fmaxf(v0, 0.f); v1 = fmaxf(v1, 0.f); }
                if (OUTF32)
                    *(float2*)(C + (size_t)r * N + c) = make_float2(v0, v1);
                if (OUTHALF)
                    *(__half2*)(Ch + (size_t)r * N + c) = __floats2half2_rn(v0, v1);
            }
        }
    }
}

// ============================================================
// Shared pieces for scores stats/emit kernels.
// Tile: 128q x 128k per block. QKV packed buffer, stride 2304.
// ============================================================
#define SPITCH 72
#define STPITCH 132

#define SCORES_PROLOG() \
    int bh = blockIdx.z, b = bh / NH, h = bh % NH; \
    int bq = blockIdx.y * 128, bk = blockIdx.x * 128; \
    const __half* Qb = QKV + (size_t)(b * SEQ) * QKVS + h * DK; \
    const __half* Kb = QKV + (size_t)(b * SEQ) * QKVS + 768 + h * DK; \
    int tid = threadIdx.x, lane = tid & 31, warp = tid >> 5; \
    int wm = warp >> 1, wn = warp & 1; \
    int g = lane >> 2, tg = lane & 3; \
    int m_l = tid & 127, part = tid >> 7; \
    { \
        const uint4* qp = (const uint4*)(Qb + (size_t)(bq + m_l) * QKVS + part * 32); \
        const uint4* kp = (const uint4*)(Kb + (size_t)(bk + m_l) * QKVS + part * 32); \
        uint4* qd = (uint4*)(su.qk.Qs + m_l * SPITCH + part * 32); \
        uint4* kd = (uint4*)(su.qk.Ks + m_l * SPITCH + part * 32); \
        _Pragma("unroll") \
        for (int j = 0; j < 4; j++) { qd[j] = qp[j]; kd[j] = kp[j]; } \
    } \
    __syncthreads(); \
    float acc[2][8][4]; \
    _Pragma("unroll") \
    for (int mt = 0; mt < 2; mt++) \
        _Pragma("unroll") \
        for (int nt = 0; nt < 8; nt++) \
            _Pragma("unroll") \
            for (int q = 0; q < 4; q++) acc[mt][nt][q] = 0.f; \
    _Pragma("unroll") \
    for (int ks16 = 0; ks16 < 64; ks16 += 16) { \
        uint32_t a[2][4]; \
        _Pragma("unroll") \
        for (int mt = 0; mt < 2; mt++) { \
            int r = wm * 32 + mt * 16 + g; \
            a[mt][0] = *(const uint32_t*)(su.qk.Qs + r*SPITCH + ks16 + tg*2); \
            a[mt][1] = *(const uint32_t*)(su.qk.Qs + (r+8)*SPITCH + ks16 + tg*2); \
            a[mt][2] = *(const uint32_t*)(su.qk.Qs + r*SPITCH + ks16 + 8 + tg*2); \
            a[mt][3] = *(const uint32_t*)(su.qk.Qs + (r+8)*SPITCH + ks16 + 8 + tg*2); \
        } \
        _Pragma("unroll") \
        for (int nt = 0; nt < 8; nt++) { \
            int cn = wn * 64 + nt * 8 + g; \
            uint32_t bfr[2]; \
            bfr[0] = *(const uint32_t*)(su.qk.Ks + cn*SPITCH + ks16 + tg*2); \
            bfr[1] = *(const uint32_t*)(su.qk.Ks + cn*SPITCH + ks16 + 8 + tg*2); \
            _Pragma("unroll") \
            for (int mt = 0; mt < 2; mt++) mma16816(acc[mt][nt], a[mt], bfr); \
        } \
    }

#define STAGE_ROUND(round) \
    __syncthreads(); \
    if ((wm >> 1) == (round)) { \
        _Pragma("unroll") \
        for (int mt = 0; mt < 2; mt++) \
            _Pragma("unroll") \
            for (int nt = 0; nt < 8; nt++) \
                _Pragma("unroll") \
                for (int hh = 0; hh < 2; hh++) { \
                    int lr = (wm & 1) * 32 + mt * 16 + g + hh * 8; \
                    int c = wn * 64 + nt * 8 + tg * 2; \
                    *(float2*)(su.stage + lr * STPITCH + c) = \
                        make_float2(acc[mt][nt][hh*2], acc[mt][nt][hh*2+1]); \
                } \
    } \
    __syncthreads();

// scores_stats: write (m_t, s_t) partials only.
__global__ __launch_bounds__(256) void scores_stats(
    const __half* __restrict__ QKV, const unsigned char* __restrict__ mask,
    float* __restrict__ partials)
{
    __shared__ union {
        struct { __half Qs[128*SPITCH]; __half Ks[128*SPITCH]; } qk;
        float stage[64*STPITCH];
    } su;
    __shared__ float red[64*4];

    SCORES_PROLOG();

    const unsigned char* mrow = mask + (size_t)b * SEQ * SEQ;
    int lr_o = tid & 63, sub = tid >> 6, cs = sub * 32;

#pragma unroll
    for (int round = 0; round < 2; round++) {
        STAGE_ROUND(round);
        int q = bq + round * 64 + lr_o;
        const unsigned char* mp = mrow + (size_t)q * SEQ + bk + cs;
        uint4 mw0 = *(const uint4*)mp;
        uint4 mw1 = *(const uint4*)(mp + 16);
        uint32_t mws[8] = {mw0.x, mw0.y, mw0.z, mw0.w, mw1.x, mw1.y, mw1.z, mw1.w};
        const float* sp = su.stage + lr_o * STPITCH + cs;
        // pass A: local max
        float lm = -1e30f;
#pragma unroll
        for (int j4 = 0; j4 < 8; j4++) {
            float4 v = *(const float4*)(sp + j4 * 4);
            v.x *= 0.125f; v.y *= 0.125f; v.z *= 0.125f; v.w *= 0.125f;
            uint32_t w = mws[j4];
            if ((w >>  0) & 0xFF) v.x = -1e9f;
            if ((w >>  8) & 0xFF) v.y = -1e9f;
            if ((w >> 16) & 0xFF) v.z = -1e9f;
            if ((w >> 24) & 0xFF) v.w = -1e9f;
            lm = fmaxf(lm, fmaxf(fmaxf(v.x, v.y), fmaxf(v.z, v.w)));
        }
        red[lr_o * 4 + sub] = lm;
        __syncthreads();
        float m_t = fmaxf(fmaxf(red[lr_o*4+0], red[lr_o*4+1]),
                          fmaxf(red[lr_o*4+2], red[lr_o*4+3]));
        // pass B: exp-sum with tile max
        float ls = 0.f;
#pragma unroll
        for (int j4 = 0; j4 < 8; j4++) {
            float4 v = *(const float4*)(sp + j4 * 4);
            v.x *= 0.125f; v.y *= 0.125f; v.z *= 0.125f; v.w *= 0.125f;
            uint32_t w = mws[j4];
            if ((w >>  0) & 0xFF) v.x = -1e9f;
            if ((w >>  8) & 0xFF) v.y = -1e9f;
            if ((w >> 16) & 0xFF) v.z = -1e9f;
            if ((w >> 24) & 0xFF) v.w = -1e9f;
            ls += __expf(v.x - m_t) + __expf(v.y - m_t)
                + __expf(v.z - m_t) + __expf(v.w - m_t);
        }
        __syncthreads();
        red[lr_o * 4 + sub] = ls;
        __syncthreads();
        if (sub == 0) {
            float s_t = red[lr_o*4+0] + red[lr_o*4+1] + red[lr_o*4+2] + red[lr_o*4+3];
            float2* pp = (float2*)partials;
            pp[((size_t)bh * 16 + blockIdx.x) * SEQ + q] = make_float2(m_t, s_t);
        }
        __syncthreads();
    }
}

// reduce partials -> (m, 1/s) per row
__global__ __launch_bounds__(256) void stats_reduce(
    const float* __restrict__ partials, float* __restrict__ stats)
{
    int gr = blockIdx.x * 256 + threadIdx.x;           // 0 .. BHN*SEQ-1
    int bh = gr >> 11, r = gr & 2047;
    const float2* pp = (const float2*)partials;
    float2 t[16];
#pragma unroll
    for (int i = 0; i < 16; i++)
        t[i] = pp[((size_t)bh * 16 + i) * SEQ + r];
    float m = t[0].x;
#pragma unroll
    for (int i = 1; i < 16; i++) m = fmaxf(m, t[i].x);
    float s = 0.f;
#pragma unroll
    for (int i = 0; i < 16; i++) s += t[i].y * __expf(t[i].x - m);
    ((float2*)stats)[gr] = make_float2(m, 1.f / s);
}

// scores_emit: recompute scores, write normalized attn f32 + fp16 copy.
__global__ __launch_bounds__(256) void scores_emit(
    const __half* __restrict__ QKV, const unsigned char* __restrict__ mask,
    const float* __restrict__ stats, float* __restrict__ P,
    __half* __restrict__ Ph)
{
    __shared__ union {
        struct { __half Qs[128*SPITCH]; __half Ks[128*SPITCH]; } qk;
        float stage[64*STPITCH];
    } su;

    SCORES_PROLOG();

    const unsigned char* mrow = mask + (size_t)b * SEQ * SEQ;
    float* Pb = P + (size_t)bh * SEQ * SEQ;
    __half* Phb = Ph + (size_t)bh * SEQ * SEQ;
    int lr_o = tid & 63, cs = (tid >> 6) * 32;

#pragma unroll
    for (int round = 0; round < 2; round++) {
        STAGE_ROUND(round);
        int q = bq + round * 64 + lr_o;
        float2 st = ((const float2*)stats)[bh * SEQ + q];
        const unsigned char* mp = mrow + (size_t)q * SEQ + bk + cs;
        uint4 mw0 = *(const uint4*)mp;
        uint4 mw1 = *(const uint4*)(mp + 16);
        uint32_t mws[8] = {mw0.x, mw0.y, mw0.z, mw0.w, mw1.x, mw1.y, mw1.z, mw1.w};
        float* op = Pb + (size_t)q * SEQ + bk + cs;
        const float* sp = su.stage + lr_o * STPITCH + cs;
        uint32_t hbuf[16];
#pragma unroll
        for (int j4 = 0; j4 < 8; j4++) {
            float4 v = *(const float4*)(sp + j4 * 4);
            v.x *= 0.125f; v.y *= 0.125f; v.z *= 0.125f; v.w *= 0.125f;
            uint32_t w = mws[j4];
            if ((w >>  0) & 0xFF) v.x = -1e9f;
            if ((w >>  8) & 0xFF) v.y = -1e9f;
            if ((w >> 16) & 0xFF) v.z = -1e9f;
            if ((w >> 24) & 0xFF) v.w = -1e9f;
            float4 p;
            p.x = __expf(v.x - st.x) * st.y;
            p.y = __expf(v.y - st.x) * st.y;
            p.z = __expf(v.z - st.x) * st.y;
            p.w = __expf(v.w - st.x) * st.y;
            *(float4*)(op + j4 * 4) = p;
            __half2 h0 = __floats2half2_rn(p.x, p.y);
            __half2 h1 = __floats2half2_rn(p.z, p.w);
            hbuf[j4*2]   = *(uint32_t*)&h0;
            hbuf[j4*2+1] = *(uint32_t*)&h1;
        }
        uint4* hp = (uint4*)(Phb + (size_t)q * SEQ + bk + cs);
#pragma unroll
        for (int j = 0; j < 4; j++)
            hp[j] = make_uint4(hbuf[j*4], hbuf[j*4+1], hbuf[j*4+2], hbuf[j*4+3]);
    }
}

// ============================================================
// PV: ctx_h = Pn(fp16)[SEQ,SEQ] @ V(fp16, packed stride). 128x64, BK=32,
// 3-stage cp.async, ldmatrix.
// ============================================================
__global__ __launch_bounds__(256, 3) void pv_h(
    const __half* __restrict__ Ph, const __half* __restrict__ QKV,
    __half* __restrict__ ctxh)
{
    __shared__ char psm[3 * 12288];
    uint32_t sb = smem_u32(psm);

    int bh = blockIdx.y, b = bh / NH, h = bh % NH;
    int bm = blockIdx.x * 128;
    const __half* Pb = Ph + (size_t)bh * SEQ * SEQ;
    const __half* Vb = QKV + (size_t)(b * SEQ) * QKVS + 1536 + h * DK;

    int tid = threadIdx.x, lane = tid & 31, warp = tid >> 5;
    int wm = warp >> 1, wn = warp & 1;
    int g = lane >> 2, tg = lane & 3;

    float acc[2][4][4];
#pragma unroll
    for (int mt = 0; mt < 2; mt++)
#pragma unroll
        for (int nt = 0; nt < 4; nt++)
#pragma unroll
            for (int q = 0; q < 4; q++) acc[mt][nt][q] = 0.f;

    int ar0 = tid >> 2, ac0 = tid & 3;
    int bk0 = tid >> 3, bc0 = tid & 7;

#define PV_LOAD(stg, k0) { \
    uint32_t base = sb + (stg) * 12288; \
    _Pragma("unroll") \
    for (int j = 0; j < 2; j++) { \
        int r = ar0 + j * 64, c = ac0; \
        uint32_t sa = base + r * 64 + ((c ^ ((r >> 1) & 3)) << 4); \
        CP_ASYNC16(sa, Pb + (size_t)(bm + r) * SEQ + (k0) + c * 8); \
    } \
    { \
        uint32_t sa = base + 8192 + bk0 * 128 + ((bc0 ^ (bk0 & 7)) << 4); \
        CP_ASYNC16(sa, Vb + (size_t)((k0) + bk0) * QKVS + bc0 * 8); \
    } \
    CP_COMMIT(); }

    PV_LOAD(0, 0);
    PV_LOAD(1, 32);

    const int NC = SEQ / 32;
    int st = 0;
    for (int i = 0; i < NC; i++) {
        CP_WAIT_GROUP(1);
        __syncthreads();
        if (i + 2 < NC) {
            int st2 = st + 2; if (st2 >= 3) st2 -= 3;
            PV_LOAD(st2, (i + 2) * 32);
        } else {
            CP_COMMIT();
        }
        uint32_t base = sb + st * 12288;
#pragma unroll
        for (int kk = 0; kk < 2; kk++) {
            int ks16 = kk * 16;
            uint32_t a[2][4];
#pragma unroll
            for (int mt = 0; mt < 2; mt++) {
                int row = wm * 32 + mt * 16 + (lane & 15);
                int ch = (ks16 >> 3) + (lane >> 4);
                uint32_t ad = base + row * 64 + ((ch ^ ((row >> 1) & 3)) << 4);
                LDSM_X4(a[mt][0], a[mt][1], a[mt][2], a[mt][3], ad);
            }
#pragma unroll
            for (int p = 0; p < 2; p++) {
                int k = ks16 + (lane & 15);
                int ch = wn * 4 + p * 2 + (lane >> 4);
                uint32_t bd = base + 8192 + k * 128 + ((ch ^ (k & 7)) << 4);
                uint32_t b0, b1, b2, b3;
                LDSM_X4T(b0, b1, b2, b3, bd);
                uint32_t f0[2] = {b0, b1}, f1[2] = {b2, b3};
#pragma unroll
                for (int mt = 0; mt < 2; mt++) {
                    mma16816(acc[mt][2*p],     a[mt], f0);
                    mma16816(acc[mt][2*p + 1], a[mt], f1);
                }
            }
        }
        st++; if (st >= 3) st = 0;
    }
#undef PV_LOAD

#pragma unroll
    for (int mt = 0; mt < 2; mt++)
#pragma unroll
        for (int nt = 0; nt < 4; nt++) {
            int dn = wn * 32 + nt * 8 + tg * 2;
#pragma unroll
            for (int hh = 0; hh < 2; hh++) {
                int r = bm + wm * 32 + mt * 16 + g + hh * 8;
                *(__half2*)(ctxh + (size_t)(b * SEQ + r) * DM + h * DK + dn) =
                    __floats2half2_rn(acc[mt][nt][hh*2], acc[mt][nt][hh*2+1]);
            }
        }
}

// ============================================================
// LayerNorm over last dim (768); optional fp16 copy of output.
// ============================================================
template<int OUTH>
__global__ __launch_bounds__(256) void layernorm_kernel(
    const float* __restrict__ X, const float* __restrict__ gam,
    const float* __restrict__ bet, float* __restrict__ Y, __half* __restrict__ Yh)
{
    int row = blockIdx.x;
    const float* x = X + (size_t)row * DM;
    float* y = Y + (size_t)row * DM;
    int tid = threadIdx.x;
    int lane = tid & 31, warp = tid >> 5;
    __shared__ float sw[8];

    float v0 = x[tid], v1 = x[tid + 256], v2 = x[tid + 512];
    float s = v0 + v1 + v2;
#pragma unroll
    for (int o = 16; o > 0; o >>= 1) s += __shfl_xor_sync(0xffffffffu, s, o);
    if (lane == 0) sw[warp] = s;
    __syncthreads();
    s = 0.f;
#pragma unroll
    for (int w = 0; w < 8; w++) s += sw[w];
    float mean = s * (1.f / 768.f);
    __syncthreads();

    float d0 = v0 - mean, d1 = v1 - mean, d2 = v2 - mean;
    float sq = d0 * d0 + d1 * d1 + d2 * d2;
#pragma unroll
    for (int o = 16; o > 0; o >>= 1) sq += __shfl_xor_sync(0xffffffffu, sq, o);
    if (lane == 0) sw[warp] = sq;
    __syncthreads();
    sq = 0.f;
#pragma unroll
    for (int w = 0; w < 8; w++) sq += sw[w];
    float var = sq * (1.f / 768.f);
    float rstd = rsqrtf(var + 1e-5f);

    float o0 = d0 * rstd * gam[tid]       + bet[tid];
    float o1 = d1 * rstd * gam[tid + 256] + bet[tid + 256];
    float o2 = d2 * rstd * gam[tid + 512] + bet[tid + 512];
    y[tid] = o0; y[tid + 256] = o1; y[tid + 512] = o2;
    if (OUTH) {
        __half* yh = Yh + (size_t)row * DM;
        yh[tid] = __float2half(o0);
        yh[tid + 256] = __float2half(o1);
        yh[tid + 512] = __float2half(o2);
    }
}

// ============================================================
#define HG_SMEM 49152

extern "C" void kernel_launch(void* const* d_in, const int* in_sizes, int n_in,
                              void* d_out, int out_size)
{
    const float* x    = (const float*)d_in[0];
    const unsigned char* mask = (const unsigned char*)d_in[1];
    const float* Wq = (const float*)d_in[2];
    const float* bq = (const float*)d_in[3];
    const float* Wk = (const float*)d_in[4];
    const float* bk = (const float*)d_in[5];
    const float* Wv = (const float*)d_in[6];
    const float* bv = (const float*)d_in[7];
    const float* Wo = (const float*)d_in[8];
    const float* bo = (const float*)d_in[9];
    const float* ln1g = (const float*)d_in[10];
    const float* ln1b = (const float*)d_in[11];
    const float* W1 = (const float*)d_in[12];
    const float* b1 = (const float*)d_in[13];
    const float* W2 = (const float*)d_in[14];
    const float* b2 = (const float*)d_in[15];
    const float* ln2g = (const float*)d_in[16];
    const float* ln2b = (const float*)d_in[17];
    float* out = (float*)d_out;

    __half *xh, *Wqkvh, *Woh, *W1h, *W2h, *qkvh, *Phh, *ctxh, *aoh, *hh;
    float *bqkv, *partials, *stats, *Pd, *t0, *ao, *f;
    cudaGetSymbolAddress((void**)&xh,    g_xh);
    cudaGetSymbolAddress((void**)&Wqkvh, g_Wqkv);
    cudaGetSymbolAddress((void**)&bqkv,  g_bqkv);
    cudaGetSymbolAddress((void**)&Woh,   g_Woh);
    cudaGetSymbolAddress((void**)&W1h,   g_W1h);
    cudaGetSymbolAddress((void**)&W2h,   g_W2h);
    cudaGetSymbolAddress((void**)&qkvh,  g_qkvh);
    cudaGetSymbolAddress((void**)&Phh,   g_Ph);
    cudaGetSymbolAddress((void**)&ctxh,  g_ctxh);
    cudaGetSymbolAddress((void**)&aoh,   g_aoh);
    cudaGetSymbolAddress((void**)&hh,    g_hh);
    cudaGetSymbolAddress((void**)&partials, g_part);
    cudaGetSymbolAddress((void**)&stats, g_stats);
    cudaGetSymbolAddress((void**)&Pd,    g_P);
    cudaGetSymbolAddress((void**)&t0,    g_t0);
    cudaGetSymbolAddress((void**)&ao,    g_ao);
    cudaGetSymbolAddress((void**)&f,     g_f);

    cudaFuncSetAttribute(hgemm<0,0,1>, cudaFuncAttributeMaxDynamicSharedMemorySize, HG_SMEM);
    cudaFuncSetAttribute(hgemm<0,1,0>, cudaFuncAttributeMaxDynamicSharedMemorySize, HG_SMEM);
    cudaFuncSetAttribute(hgemm<1,0,1>, cudaFuncAttributeMaxDynamicSharedMemorySize, HG_SMEM);

    float* Pbuf = ((size_t)out_size >= (size_t)OUT_ELEMS + ATT_ELEMS)
                ? (out + OUT_ELEMS) : Pd;

    f2h_kernel<<<(MROWS*DM)/1024, 256>>>(x,  xh);
    pack_qkv_w<<<(DM*QKVS)/1024, 256>>>(Wq, Wk, Wv, Wqkvh);
    pack_qkv_b<<<(QKVS + 255)/256, 256>>>(bq, bk, bv, bqkv);
    f2h_kernel<<<(DM*DM)/1024,  256>>>(Wo, Woh);
    f2h_kernel<<<(DM*DFF)/1024, 256>>>(W1, W1h);
    f2h_kernel<<<(DFF*DM)/1024, 256>>>(W2, W2h);

    // packed QKV projection: [4096, 2304]
    hgemm<0,0,1><<<dim3(QKVS/128, MROWS/128), 256, HG_SMEM>>>(
        xh, Wqkvh, bqkv, nullptr, nullptr, qkvh, MROWS, QKVS, DM);

    dim3 gs(SEQ / 128, SEQ / 128, BHN);
    scores_stats<<<gs, 256>>>(qkvh, mask, partials);
    stats_reduce<<<(BHN*SEQ)/256, 256>>>(partials, stats);
    scores_emit<<<gs, 256>>>(qkvh, mask, stats, Pbuf, Phh);

    dim3 gpv(SEQ / 128, BHN);
    pv_h<<<gpv, 256>>>(Phh, qkvh, ctxh);

    dim3 g768(DM / 128, MROWS / 128);
    hgemm<0,1,0><<<g768, 256, HG_SMEM>>>(ctxh, Woh, bo, x, t0, nullptr, MROWS, DM, DM);
    layernorm_kernel<1><<<MROWS, 256>>>(t0, ln1g, ln1b, ao, aoh);

    dim3 gff1(DFF / 128, MROWS / 128);
    hgemm<1,0,1><<<gff1, 256, HG_SMEM>>>(aoh, W1h, b1, nullptr, nullptr, hh, MROWS, DFF, DM);
    hgemm<0,1,0><<<g768, 256, HG_SMEM>>>(hh, W2h, b2, ao, f, nullptr, MROWS, DM, DFF);
    layernorm_kernel<0><<<MROWS, 256>>>(f, ln2g, ln2b, out, nullptr);
}

// round 16
// speedup vs baseline: 1.1991x; 1.1991x over previous
#include <cuda_runtime.h>
#include <cuda_fp16.h>
#include <math.h>
#include <stdint.h>

#define DM 768
#define DFF 3072
#define NH 12
#define DK 64
#define BATCH 2
#define SEQ 2048
#define MROWS (BATCH*SEQ)            // 4096
#define BHN (BATCH*NH)               // 24
#define QKVS 2304                    // packed QKV row stride
#define OUT_ELEMS (MROWS*DM)
#define ATT_ELEMS ((size_t)BHN*SEQ*SEQ)

// ---- scratch (allocation-free: __device__ globals) ----
__device__ __align__(16) __half g_xh  [MROWS*DM];
__device__ __align__(16) __half g_Wqkv[DM*QKVS];
__device__ __align__(16) float  g_bqkv[QKVS];
__device__ __align__(16) __half g_Woh[DM*DM];
__device__ __align__(16) __half g_W1h[DM*DFF];
__device__ __align__(16) __half g_W2h[DFF*DM];
__device__ __align__(16) __half g_qkvh[MROWS*QKVS];
__device__ __align__(16) __half g_Ph [BHN*(size_t)SEQ*SEQ];  // fp16 normalized P
__device__ __align__(16) __half g_ctxh[MROWS*DM];
__device__ __align__(16) __half g_aoh[MROWS*DM];
__device__ __align__(16) __half g_hh [MROWS*DFF];
__device__ __align__(16) float  g_P[BHN*(size_t)SEQ*SEQ];    // fallback attn
__device__ __align__(16) float  g_t0[MROWS*DM];
__device__ __align__(16) float  g_ao[MROWS*DM];
__device__ __align__(16) float  g_f [MROWS*DM];

__device__ __forceinline__ uint32_t smem_u32(const void* p) {
    uint32_t a;
    asm("{ .reg .u64 t; cvta.to.shared.u64 t, %1; cvt.u32.u64 %0, t; }"
        : "=r"(a) : "l"(p));
    return a;
}

__device__ __forceinline__ void mma16816(float* c, const uint32_t* a, const uint32_t* b) {
    asm volatile(
        "mma.sync.aligned.m16n8k16.row.col.f32.f16.f16.f32 "
        "{%0,%1,%2,%3}, {%4,%5,%6,%7}, {%8,%9}, {%0,%1,%2,%3};"
        : "+f"(c[0]), "+f"(c[1]), "+f"(c[2]), "+f"(c[3])
        : "r"(a[0]), "r"(a[1]), "r"(a[2]), "r"(a[3]), "r"(b[0]), "r"(b[1]));
}

#define LDSM_X4(r0,r1,r2,r3,addr) \
    asm volatile("ldmatrix.sync.aligned.m8n8.x4.shared.b16 {%0,%1,%2,%3}, [%4];" \
        : "=r"(r0),"=r"(r1),"=r"(r2),"=r"(r3) : "r"(addr))
#define LDSM_X4T(r0,r1,r2,r3,addr) \
    asm volatile("ldmatrix.sync.aligned.m8n8.x4.trans.shared.b16 {%0,%1,%2,%3}, [%4];" \
        : "=r"(r0),"=r"(r1),"=r"(r2),"=r"(r3) : "r"(addr))
#define CP_ASYNC16(saddr, gptr) \
    asm volatile("cp.async.cg.shared.global [%0], [%1], 16;" :: "r"(saddr), "l"(gptr))
#define CP_COMMIT() asm volatile("cp.async.commit_group;")
#define CP_WAIT_GROUP(n) asm volatile("cp.async.wait_group %0;" :: "n"(n))

// ============================================================
// f32 -> f16 convert
// ============================================================
__global__ __launch_bounds__(256) void f2h_kernel(
    const float* __restrict__ X, __half* __restrict__ Y)
{
    int i = (blockIdx.x * 256 + threadIdx.x) * 4;
    float4 v = *(const float4*)(X + i);
    *(__half2*)(Y + i)     = __floats2half2_rn(v.x, v.y);
    *(__half2*)(Y + i + 2) = __floats2half2_rn(v.z, v.w);
}

// ============================================================
// pack Wq|Wk|Wv -> [768, 2304] fp16 ; biases -> [2304] f32
// ============================================================
__global__ __launch_bounds__(256) void pack_qkv_w(
    const float* __restrict__ Wq, const float* __restrict__ Wk,
    const float* __restrict__ Wv, __half* __restrict__ Wout)
{
    int i = (blockIdx.x * 256 + threadIdx.x) * 4;
    int r = i / QKVS, c = i % QKVS;
    const float* src; int cc;
    if (c < 768)       { src = Wq; cc = c; }
    else if (c < 1536) { src = Wk; cc = c - 768; }
    else               { src = Wv; cc = c - 1536; }
    float4 v = *(const float4*)(src + (size_t)r * DM + cc);
    *(__half2*)(Wout + i)     = __floats2half2_rn(v.x, v.y);
    *(__half2*)(Wout + i + 2) = __floats2half2_rn(v.z, v.w);
}

__global__ __launch_bounds__(256) void pack_qkv_b(
    const float* __restrict__ bq, const float* __restrict__ bk,
    const float* __restrict__ bv, float* __restrict__ bout)
{
    int c = blockIdx.x * 256 + threadIdx.x;
    if (c >= QKVS) return;
    float v;
    if (c < 768)       v = bq[c];
    else if (c < 1536) v = bk[c - 768];
    else               v = bv[c - 1536];
    bout[c] = v;
}

// ============================================================
// fp16 GEMM: 128x128x32, 3-stage cp.async, ldmatrix frags, 8 warps.
// ============================================================
template<int RELU, int OUTF32, int OUTHALF>
__global__ __launch_bounds__(256, 2) void hgemm(
    const __half* __restrict__ A, const __half* __restrict__ W,
    const float* __restrict__ bias, const float* __restrict__ resid,
    float* __restrict__ C, __half* __restrict__ Ch,
    int M, int N, int K)
{
    extern __shared__ char dsm[];
    uint32_t sb = smem_u32(dsm);

    int tid = threadIdx.x, lane = tid & 31, warp = tid >> 5;
    int wm = warp >> 1, wn = warp & 1;
    int g = lane >> 2, tg = lane & 3;
    int bm = blockIdx.y * 128, bn = blockIdx.x * 128;

    float acc[2][8][4];
#pragma unroll
    for (int mt = 0; mt < 2; mt++)
#pragma unroll
        for (int nt = 0; nt < 8; nt++)
#pragma unroll
            for (int q = 0; q < 4; q++) acc[mt][nt][q] = 0.f;

    const int NC = K / 32;
    int ar0 = tid >> 2, ac0 = tid & 3;
    int bk0 = tid >> 4, bc0 = tid & 15;

#define LOAD_STAGE(stg, k0) { \
    uint32_t base = sb + (stg) * 16384; \
    _Pragma("unroll") \
    for (int j = 0; j < 2; j++) { \
        int r = ar0 + j * 64, c = ac0; \
        uint32_t sa = base + r * 64 + ((c ^ ((r >> 1) & 3)) << 4); \
        CP_ASYNC16(sa, A + (size_t)(bm + r) * K + (k0) + c * 8); \
    } \
    _Pragma("unroll") \
    for (int j = 0; j < 2; j++) { \
        int k = bk0 + j * 16, c = bc0; \
        uint32_t sa = base + 8192 + k * 256 + ((c ^ (k & 7)) << 4); \
        CP_ASYNC16(sa, W + (size_t)((k0) + k) * N + bn + c * 8); \
    } \
    CP_COMMIT(); }

    LOAD_STAGE(0, 0);
    LOAD_STAGE(1, 32);

    int st = 0;
    for (int i = 0; i < NC; i++) {
        CP_WAIT_GROUP(1);
        __syncthreads();
        if (i + 2 < NC) {
            int st2 = st + 2; if (st2 >= 3) st2 -= 3;
            LOAD_STAGE(st2, (i + 2) * 32);
        } else {
            CP_COMMIT();
        }
        uint32_t base = sb + st * 16384;
#pragma unroll
        for (int kk = 0; kk < 2; kk++) {
            int ks16 = kk * 16;
            uint32_t a[2][4];
#pragma unroll
            for (int mt = 0; mt < 2; mt++) {
                int row = wm * 32 + mt * 16 + (lane & 15);
                int ch = (ks16 >> 3) + (lane >> 4);
                uint32_t ad = base + row * 64 + ((ch ^ ((row >> 1) & 3)) << 4);
                LDSM_X4(a[mt][0], a[mt][1], a[mt][2], a[mt][3], ad);
            }
#pragma unroll
            for (int p = 0; p < 4; p++) {
                int k = ks16 + (lane & 15);
                int ch = wn * 8 + p * 2 + (lane >> 4);
                uint32_t bd = base + 8192 + k * 256 + ((ch ^ (k & 7)) << 4);
                uint32_t b0, b1, b2, b3;
                LDSM_X4T(b0, b1, b2, b3, bd);
                uint32_t f0[2] = {b0, b1}, f1[2] = {b2, b3};
#pragma unroll
                for (int mt = 0; mt < 2; mt++) {
                    mma16816(acc[mt][2*p],     a[mt], f0);
                    mma16816(acc[mt][2*p + 1], a[mt], f1);
                }
            }
        }
        st++; if (st >= 3) st = 0;
    }
#undef LOAD_STAGE

#pragma unroll
    for (int mt = 0; mt < 2; mt++) {
#pragma unroll
        for (int nt = 0; nt < 8; nt++) {
            int c = bn + wn * 64 + nt * 8 + tg * 2;
            float bx = bias[c], by = bias[c + 1];
#pragma unroll
            for (int hh = 0; hh < 2; hh++) {
                int r = bm + wm * 32 + mt * 16 + g + hh * 8;
                float v0 = acc[mt][nt][hh*2+0] + bx;
                float v1 = acc[mt][nt][hh*2+1] + by;
                if (OUTF32 && resid) {
                    float2 rv = *(const float2*)(resid + (size_t)r * N + c);
                    v0 += rv.x; v1 += rv.y;
                }
                if (RELU) { v0 = fmaxf(v0, 0.f); v1 = fmaxf(v1, 0.f); }
                if (OUTF32)
                    *(float2*)(C + (size_t)r * N + c) = make_float2(v0, v1);
                if (OUTHALF)
                    *(__half2*)(Ch + (size_t)r * N + c) = __floats2half2_rn(v0, v1);
            }
        }
    }
}

// ============================================================
// Scores: P[bh,q,k] = (Q.K)/8 masked, raw f32 out. cp.async + ldmatrix.
// Q/K tiles 128x64h (128B pitch, swz ch^(r&7)). Stage epilogue as R14.
// smem: union{ tiles 32KB ; stage 33.8KB } = 33792 B static.
// ============================================================
#define STPITCH 132

__global__ __launch_bounds__(256) void scores_mma(
    const __half* __restrict__ QKV, const unsigned char* __restrict__ mask,
    float* __restrict__ P)
{
    __shared__ union {
        char tiles[2 * 16384];            // Q at 0, K at 16384
        float stage[64 * STPITCH];
    } su;
    uint32_t sb = smem_u32(su.tiles);

    int bh = blockIdx.z, b = bh / NH, h = bh % NH;
    int bq = blockIdx.y * 128, bk = blockIdx.x * 128;
    const __half* Qb = QKV + (size_t)(b * SEQ) * QKVS + h * DK;
    const __half* Kb = QKV + (size_t)(b * SEQ) * QKVS + 768 + h * DK;

    int tid = threadIdx.x, lane = tid & 31, warp = tid >> 5;
    int wm = warp >> 1, wn = warp & 1;
    int g = lane >> 2, tg = lane & 3;

    // load Q,K tiles: 2 threads/row, 4 chunks of 16B each
    {
        int lr = tid >> 1, lc0 = (tid & 1) * 4;
#pragma unroll
        for (int j = 0; j < 4; j++) {
            int ch = lc0 + j;
            uint32_t sw = ((ch ^ (lr & 7)) << 4);
            CP_ASYNC16(sb + lr * 128 + sw, Qb + (size_t)(bq + lr) * QKVS + ch * 8);
            CP_ASYNC16(sb + 16384 + lr * 128 + sw, Kb + (size_t)(bk + lr) * QKVS + ch * 8);
        }
        CP_COMMIT();
    }
    CP_WAIT_GROUP(0);
    __syncthreads();

    // Q fragments
    uint32_t aq[2][4][4];
#pragma unroll
    for (int mt = 0; mt < 2; mt++)
#pragma unroll
        for (int kg = 0; kg < 4; kg++) {
            int row = wm * 32 + mt * 16 + (lane & 15);
            int ch = (kg << 1) + (lane >> 4);
            uint32_t ad = sb + row * 128 + ((ch ^ (row & 7)) << 4);
            LDSM_X4(aq[mt][kg][0], aq[mt][kg][1], aq[mt][kg][2], aq[mt][kg][3], ad);
        }

    float acc[2][8][4];
#pragma unroll
    for (int mt = 0; mt < 2; mt++)
#pragma unroll
        for (int nt = 0; nt < 8; nt++)
#pragma unroll
            for (int q = 0; q < 4; q++) acc[mt][nt][q] = 0.f;

#pragma unroll
    for (int kg = 0; kg < 4; kg++) {
#pragma unroll
        for (int np = 0; np < 4; np++) {
            int n0 = wn * 64 + np * 16;
            int row = n0 + (lane & 7) + ((lane >> 4) << 3);
            int ch = (kg << 1) + ((lane >> 3) & 1);
            uint32_t ad = sb + 16384 + row * 128 + ((ch ^ (row & 7)) << 4);
            uint32_t b0, b1, b2, b3;
            LDSM_X4(b0, b1, b2, b3, ad);
            uint32_t f0[2] = {b0, b1}, f1[2] = {b2, b3};
#pragma unroll
            for (int mt = 0; mt < 2; mt++) {
                mma16816(acc[mt][np*2],     aq[mt][kg], f0);
                mma16816(acc[mt][np*2 + 1], aq[mt][kg], f1);
            }
        }
    }

    const unsigned char* mrow = mask + (size_t)b * SEQ * SEQ;
    float* Pb = P + (size_t)bh * SEQ * SEQ;

    int lr_o = tid & 63, cs = (tid >> 6) * 32;
#pragma unroll
    for (int round = 0; round < 2; round++) {
        __syncthreads();
        if ((wm >> 1) == round) {
#pragma unroll
            for (int mt = 0; mt < 2; mt++)
#pragma unroll
                for (int nt = 0; nt < 8; nt++)
#pragma unroll
                    for (int hh = 0; hh < 2; hh++) {
                        int lr = (wm & 1) * 32 + mt * 16 + g + hh * 8;
                        int c = wn * 64 + nt * 8 + tg * 2;
                        *(float2*)(su.stage + lr * STPITCH + c) =
                            make_float2(acc[mt][nt][hh*2], acc[mt][nt][hh*2+1]);
                    }
        }
        __syncthreads();
        {
            int q = bq + round * 64 + lr_o;
            const unsigned char* mp = mrow + (size_t)q * SEQ + bk + cs;
            uint4 mw0 = *(const uint4*)mp;
            uint4 mw1 = *(const uint4*)(mp + 16);
            uint32_t mws[8] = {mw0.x, mw0.y, mw0.z, mw0.w, mw1.x, mw1.y, mw1.z, mw1.w};
            float* op = Pb + (size_t)q * SEQ + bk + cs;
            const float* sp = su.stage + lr_o * STPITCH + cs;
#pragma unroll
            for (int j4 = 0; j4 < 8; j4++) {
                float4 v = *(const float4*)(sp + j4 * 4);
                v.x *= 0.125f; v.y *= 0.125f; v.z *= 0.125f; v.w *= 0.125f;
                uint32_t w = mws[j4];
                if ((w >>  0) & 0xFF) v.x = -1e9f;
                if ((w >>  8) & 0xFF) v.y = -1e9f;
                if ((w >> 16) & 0xFF) v.z = -1e9f;
                if ((w >> 24) & 0xFF) v.w = -1e9f;
                *(float4*)(op + j4 * 4) = v;
            }
        }
    }
}

// ============================================================
// Row softmax over SEQ=2048, in place (f32) + fp16 copy for PV.
// ============================================================
__global__ __launch_bounds__(128) void softmax_kernel(
    float* __restrict__ P, __half* __restrict__ Ph)
{
    size_t row = blockIdx.x;
    float* p = P + row * (size_t)SEQ;
    __half* ph = Ph + row * (size_t)SEQ;
    int tid = threadIdx.x;
    int lane = tid & 31, warp = tid >> 5;
    __shared__ float sred[4];

    float4 v[4];
    float m = -1e30f;
#pragma unroll
    for (int i = 0; i < 4; i++) {
        v[i] = *(const float4*)(p + i * 512 + tid * 4);
        m = fmaxf(m, fmaxf(fmaxf(v[i].x, v[i].y), fmaxf(v[i].z, v[i].w)));
    }
#pragma unroll
    for (int o = 16; o > 0; o >>= 1) m = fmaxf(m, __shfl_xor_sync(0xffffffffu, m, o));
    if (lane == 0) sred[warp] = m;
    __syncthreads();
    m = fmaxf(fmaxf(sred[0], sred[1]), fmaxf(sred[2], sred[3]));
    __syncthreads();

    float s = 0.f;
#pragma unroll
    for (int i = 0; i < 4; i++) {
        v[i].x = __expf(v[i].x - m); v[i].y = __expf(v[i].y - m);
        v[i].z = __expf(v[i].z - m); v[i].w = __expf(v[i].w - m);
        s += v[i].x + v[i].y + v[i].z + v[i].w;
    }
#pragma unroll
    for (int o = 16; o > 0; o >>= 1) s += __shfl_xor_sync(0xffffffffu, s, o);
    if (lane == 0) sred[warp] = s;
    __syncthreads();
    s = sred[0] + sred[1] + sred[2] + sred[3];
    float inv = 1.f / s;
#pragma unroll
    for (int i = 0; i < 4; i++) {
        v[i].x *= inv; v[i].y *= inv; v[i].z *= inv; v[i].w *= inv;
        *(float4*)(p + i * 512 + tid * 4) = v[i];
        __half2 h0 = __floats2half2_rn(v[i].x, v[i].y);
        __half2 h1 = __floats2half2_rn(v[i].z, v[i].w);
        *(uint2*)(ph + i * 512 + tid * 4) =
            make_uint2(*(uint32_t*)&h0, *(uint32_t*)&h1);
    }
}

// ============================================================
// PV: ctx_h = Pn(fp16)[SEQ,SEQ] @ V(fp16, packed stride). 128x64, BK=32,
// 3-stage cp.async, ldmatrix.
// ============================================================
__global__ __launch_bounds__(256, 3) void pv_h(
    const __half* __restrict__ Ph, const __half* __restrict__ QKV,
    __half* __restrict__ ctxh)
{
    __shared__ char psm[3 * 12288];
    uint32_t sb = smem_u32(psm);

    int bh = blockIdx.y, b = bh / NH, h = bh % NH;
    int bm = blockIdx.x * 128;
    const __half* Pb = Ph + (size_t)bh * SEQ * SEQ;
    const __half* Vb = QKV + (size_t)(b * SEQ) * QKVS + 1536 + h * DK;

    int tid = threadIdx.x, lane = tid & 31, warp = tid >> 5;
    int wm = warp >> 1, wn = warp & 1;
    int g = lane >> 2, tg = lane & 3;

    float acc[2][4][4];
#pragma unroll
    for (int mt = 0; mt < 2; mt++)
#pragma unroll
        for (int nt = 0; nt < 4; nt++)
#pragma unroll
            for (int q = 0; q < 4; q++) acc[mt][nt][q] = 0.f;

    int ar0 = tid >> 2, ac0 = tid & 3;
    int bk0 = tid >> 3, bc0 = tid & 7;

#define PV_LOAD(stg, k0) { \
    uint32_t base = sb + (stg) * 12288; \
    _Pragma("unroll") \
    for (int j = 0; j < 2; j++) { \
        int r = ar0 + j * 64, c = ac0; \
        uint32_t sa = base + r * 64 + ((c ^ ((r >> 1) & 3)) << 4); \
        CP_ASYNC16(sa, Pb + (size_t)(bm + r) * SEQ + (k0) + c * 8); \
    } \
    { \
        uint32_t sa = base + 8192 + bk0 * 128 + ((bc0 ^ (bk0 & 7)) << 4); \
        CP_ASYNC16(sa, Vb + (size_t)((k0) + bk0) * QKVS + bc0 * 8); \
    } \
    CP_COMMIT(); }

    PV_LOAD(0, 0);
    PV_LOAD(1, 32);

    const int NC = SEQ / 32;
    int st = 0;
    for (int i = 0; i < NC; i++) {
        CP_WAIT_GROUP(1);
        __syncthreads();
        if (i + 2 < NC) {
            int st2 = st + 2; if (st2 >= 3) st2 -= 3;
            PV_LOAD(st2, (i + 2) * 32);
        } else {
            CP_COMMIT();
        }
        uint32_t base = sb + st * 12288;
#pragma unroll
        for (int kk = 0; kk < 2; kk++) {
            int ks16 = kk * 16;
            uint32_t a[2][4];
#pragma unroll
            for (int mt = 0; mt < 2; mt++) {
                int row = wm * 32 + mt * 16 + (lane & 15);
                int ch = (ks16 >> 3) + (lane >> 4);
                uint32_t ad = base + row * 64 + ((ch ^ ((row >> 1) & 3)) << 4);
                LDSM_X4(a[mt][0], a[mt][1], a[mt][2], a[mt][3], ad);
            }
#pragma unroll
            for (int p = 0; p < 2; p++) {
                int k = ks16 + (lane & 15);
                int ch = wn * 4 + p * 2 + (lane >> 4);
                uint32_t bd = base + 8192 + k * 128 + ((ch ^ (k & 7)) << 4);
                uint32_t b0, b1, b2, b3;
                LDSM_X4T(b0, b1, b2, b3, bd);
                uint32_t f0[2] = {b0, b1}, f1[2] = {b2, b3};
#pragma unroll
                for (int mt = 0; mt < 2; mt++) {
                    mma16816(acc[mt][2*p],     a[mt], f0);
                    mma16816(acc[mt][2*p + 1], a[mt], f1);
                }
            }
        }
        st++; if (st >= 3) st = 0;
    }
#undef PV_LOAD

#pragma unroll
    for (int mt = 0; mt < 2; mt++)
#pragma unroll
        for (int nt = 0; nt < 4; nt++) {
            int dn = wn * 32 + nt * 8 + tg * 2;
#pragma unroll
            for (int hh = 0; hh < 2; hh++) {
                int r = bm + wm * 32 + mt * 16 + g + hh * 8;
                *(__half2*)(ctxh + (size_t)(b * SEQ + r) * DM + h * DK + dn) =
                    __floats2half2_rn(acc[mt][nt][hh*2], acc[mt][nt][hh*2+1]);
            }
        }
}

// ============================================================
// LayerNorm over last dim (768); optional fp16 copy of output.
// ============================================================
template<int OUTH>
__global__ __launch_bounds__(256) void layernorm_kernel(
    const float* __restrict__ X, const float* __restrict__ gam,
    const float* __restrict__ bet, float* __restrict__ Y, __half* __restrict__ Yh)
{
    int row = blockIdx.x;
    const float* x = X + (size_t)row * DM;
    float* y = Y + (size_t)row * DM;
    int tid = threadIdx.x;
    int lane = tid & 31, warp = tid >> 5;
    __shared__ float sw[8];

    float v0 = x[tid], v1 = x[tid + 256], v2 = x[tid + 512];
    float s = v0 + v1 + v2;
#pragma unroll
    for (int o = 16; o > 0; o >>= 1) s += __shfl_xor_sync(0xffffffffu, s, o);
    if (lane == 0) sw[warp] = s;
    __syncthreads();
    s = 0.f;
#pragma unroll
    for (int w = 0; w < 8; w++) s += sw[w];
    float mean = s * (1.f / 768.f);
    __syncthreads();

    float d0 = v0 - mean, d1 = v1 - mean, d2 = v2 - mean;
    float sq = d0 * d0 + d1 * d1 + d2 * d2;
#pragma unroll
    for (int o = 16; o > 0; o >>= 1) sq += __shfl_xor_sync(0xffffffffu, sq, o);
    if (lane == 0) sw[warp] = sq;
    __syncthreads();
    sq = 0.f;
#pragma unroll
    for (int w = 0; w < 8; w++) sq += sw[w];
    float var = sq * (1.f / 768.f);
    float rstd = rsqrtf(var + 1e-5f);

    float o0 = d0 * rstd * gam[tid]       + bet[tid];
    float o1 = d1 * rstd * gam[tid + 256] + bet[tid + 256];
    float o2 = d2 * rstd * gam[tid + 512] + bet[tid + 512];
    y[tid] = o0; y[tid + 256] = o1; y[tid + 512] = o2;
    if (OUTH) {
        __half* yh = Yh + (size_t)row * DM;
        yh[tid] = __float2half(o0);
        yh[tid + 256] = __float2half(o1);
        yh[tid + 512] = __float2half(o2);
    }
}

// ============================================================
#define HG_SMEM 49152

extern "C" void kernel_launch(void* const* d_in, const int* in_sizes, int n_in,
                              void* d_out, int out_size)
{
    const float* x    = (const float*)d_in[0];
    const unsigned char* mask = (const unsigned char*)d_in[1];
    const float* Wq = (const float*)d_in[2];
    const float* bq = (const float*)d_in[3];
    const float* Wk = (const float*)d_in[4];
    const float* bk = (const float*)d_in[5];
    const float* Wv = (const float*)d_in[6];
    const float* bv = (const float*)d_in[7];
    const float* Wo = (const float*)d_in[8];
    const float* bo = (const float*)d_in[9];
    const float* ln1g = (const float*)d_in[10];
    const float* ln1b = (const float*)d_in[11];
    const float* W1 = (const float*)d_in[12];
    const float* b1 = (const float*)d_in[13];
    const float* W2 = (const float*)d_in[14];
    const float* b2 = (const float*)d_in[15];
    const float* ln2g = (const float*)d_in[16];
    const float* ln2b = (const float*)d_in[17];
    float* out = (float*)d_out;

    __half *xh, *Wqkvh, *Woh, *W1h, *W2h, *qkvh, *Phh, *ctxh, *aoh, *hh;
    float *bqkv, *Pd, *t0, *ao, *f;
    cudaGetSymbolAddress((void**)&xh,    g_xh);
    cudaGetSymbolAddress((void**)&Wqkvh, g_Wqkv);
    cudaGetSymbolAddress((void**)&bqkv,  g_bqkv);
    cudaGetSymbolAddress((void**)&Woh,   g_Woh);
    cudaGetSymbolAddress((void**)&W1h,   g_W1h);
    cudaGetSymbolAddress((void**)&W2h,   g_W2h);
    cudaGetSymbolAddress((void**)&qkvh,  g_qkvh);
    cudaGetSymbolAddress((void**)&Phh,   g_Ph);
    cudaGetSymbolAddress((void**)&ctxh,  g_ctxh);
    cudaGetSymbolAddress((void**)&aoh,   g_aoh);
    cudaGetSymbolAddress((void**)&hh,    g_hh);
    cudaGetSymbolAddress((void**)&Pd,    g_P);
    cudaGetSymbolAddress((void**)&t0,    g_t0);
    cudaGetSymbolAddress((void**)&ao,    g_ao);
    cudaGetSymbolAddress((void**)&f,     g_f);

    cudaFuncSetAttribute(hgemm<0,0,1>, cudaFuncAttributeMaxDynamicSharedMemorySize, HG_SMEM);
    cudaFuncSetAttribute(hgemm<0,1,0>, cudaFuncAttributeMaxDynamicSharedMemorySize, HG_SMEM);
    cudaFuncSetAttribute(hgemm<1,0,1>, cudaFuncAttributeMaxDynamicSharedMemorySize, HG_SMEM);

    float* Pbuf = ((size_t)out_size >= (size_t)OUT_ELEMS + ATT_ELEMS)
                ? (out + OUT_ELEMS) : Pd;

    f2h_kernel<<<(MROWS*DM)/1024, 256>>>(x,  xh);
    pack_qkv_w<<<(DM*QKVS)/1024, 256>>>(Wq, Wk, Wv, Wqkvh);
    pack_qkv_b<<<(QKVS + 255)/256, 256>>>(bq, bk, bv, bqkv);
    f2h_kernel<<<(DM*DM)/1024,  256>>>(Wo, Woh);
    f2h_kernel<<<(DM*DFF)/1024, 256>>>(W1, W1h);
    f2h_kernel<<<(DFF*DM)/1024, 256>>>(W2, W2h);

    // packed QKV projection: [4096, 2304]
    hgemm<0,0,1><<<dim3(QKVS/128, MROWS/128), 256, HG_SMEM>>>(
        xh, Wqkvh, bqkv, nullptr, nullptr, qkvh, MROWS, QKVS, DM);

    dim3 gs(SEQ / 128, SEQ / 128, BHN);
    scores_mma<<<gs, 256>>>(qkvh, mask, Pbuf);
    softmax_kernel<<<BHN * SEQ, 128>>>(Pbuf, Phh);

    dim3 gpv(SEQ / 128, BHN);
    pv_h<<<gpv, 256>>>(Phh, qkvh, ctxh);

    dim3 g768(DM / 128, MROWS / 128);
    hgemm<0,1,0><<<g768, 256, HG_SMEM>>>(ctxh, Woh, bo, x, t0, nullptr, MROWS, DM, DM);
    layernorm_kernel<1><<<MROWS, 256>>>(t0, ln1g, ln1b, ao, aoh);

    dim3 gff1(DFF / 128, MROWS / 128);
    hgemm<1,0,1><<<gff1, 256, HG_SMEM>>>(aoh, W1h, b1, nullptr, nullptr, hh, MROWS, DFF, DM);
    hgemm<0,1,0><<<g768, 256, HG_SMEM>>>(hh, W2h, b2, ao, f, nullptr, MROWS, DM, DFF);
    layernorm_kernel<0><<<MROWS, 256>>>(f, ln2g, ln2b, out, nullptr);
}